// round 6
// baseline (speedup 1.0000x reference)
#include <cuda_runtime.h>
#include <cstdint>

using ull = unsigned long long;

constexpr int S  = 1024;
constexpr int HD = 256;
constexpr int NB = 128;

// Precomputed input projections: XG[b][s][gate*256 + j], gate order z,r,c
__device__ float XG_buf[(size_t)NB * S * 768];

__device__ __forceinline__ void ffma2(ull& d, ull a, ull b) {
    asm("fma.rn.f32x2 %0, %1, %2, %0;" : "+l"(d) : "l"(a), "l"(b));
}
__device__ __forceinline__ float2 unpk(ull a) {
    float2 r; asm("mov.b64 {%0, %1}, %2;" : "=f"(r.x), "=f"(r.y) : "l"(a)); return r;
}
__device__ __forceinline__ uint32_t smem_u32(const void* p) {
    uint32_t a;
    asm("{ .reg .u64 t; cvta.to.shared.u64 t, %1; cvt.u32.u64 %0, t; }" : "=r"(a) : "l"(p));
    return a;
}
__device__ __forceinline__ uint32_t mapa_rank(uint32_t addr, uint32_t rank) {
    uint32_t r; asm("mapa.shared::cluster.u32 %0, %1, %2;" : "=r"(r) : "r"(addr), "r"(rank));
    return r;
}
__device__ __forceinline__ void st_clu_v4(uint32_t addr, float4 v) {
    asm volatile("st.shared::cluster.v4.f32 [%0], {%1,%2,%3,%4};"
                 :: "r"(addr), "f"(v.x), "f"(v.y), "f"(v.z), "f"(v.w) : "memory");
}
__device__ __forceinline__ void clu_arrive() {
    asm volatile("barrier.cluster.arrive.aligned;" ::: "memory");
}
__device__ __forceinline__ void clu_wait() {
    asm volatile("barrier.cluster.wait.aligned;" ::: "memory");
}
__device__ __forceinline__ void mbar_init(uint32_t addr, uint32_t cnt) {
    asm volatile("mbarrier.init.shared.b64 [%0], %1;" :: "r"(addr), "r"(cnt) : "memory");
}
__device__ __forceinline__ void mbar_arrive_remote(uint32_t addr) {
    asm volatile("mbarrier.arrive.release.cluster.shared::cluster.b64 _, [%0];"
                 :: "r"(addr) : "memory");
}
__device__ __forceinline__ void mbar_wait(uint32_t addr, uint32_t parity) {
    asm volatile(
        "{\n\t.reg .pred P;\n\t"
        "LW%=:\n\t"
        "mbarrier.try_wait.parity.acquire.cluster.shared::cta.b64 P, [%0], %1, 0x989680;\n\t"
        "@P bra LD%=;\n\t"
        "bra LW%=;\n\t"
        "LD%=:\n\t}"
        :: "r"(addr), "r"(parity) : "memory");
}
__device__ __forceinline__ float sigm(float x) { return 1.0f / (1.0f + __expf(-x)); }
__device__ __forceinline__ float tanh_f(float x) {
    x = fminf(fmaxf(x, -15.0f), 15.0f);
    float e = __expf(-2.0f * x);
    return __fdividef(1.0f - e, 1.0f + e);
}
// quad rotation swizzle: logical quad q (0..63) -> physical quad within a row
__device__ __forceinline__ int swq(int q) { return (q & ~7) | ((q + (q >> 3)) & 7); }

// ============================================================================
// Phase 1: XG = x @ Wg^T + bias. Lane = m-row (X lane-indexed, W broadcast).
// grid = 12 n-tiles * 128 m-groups, 512 threads. Warp = (m-group 32) x (j-group 16).
// ============================================================================
constexpr int XS_OFF = 0;               // [128][260]
constexpr int WS_OFF = 128 * 260;       // [64][260]
constexpr int PRE_FLOATS = 128 * 260 + 64 * 260;
constexpr size_t PRE_SMEM_BYTES = PRE_FLOATS * sizeof(float);   // 199680

__global__ void __launch_bounds__(512, 1)
xproj_kernel(const float* __restrict__ x,
             const float* __restrict__ Wzx, const float* __restrict__ bz,
             const float* __restrict__ Wrx, const float* __restrict__ br,
             const float* __restrict__ Wcx, const float* __restrict__ bc)
{
    extern __shared__ float smp[];
    float* XS = smp + XS_OFF;
    float* WS = smp + WS_OFF;

    const int tid = threadIdx.x, w = tid >> 5, lane = tid & 31;
    const int nt = blockIdx.x % 12, mg = blockIdx.x / 12;
    const int gate = nt >> 2, j0 = (nt & 3) * 64;
    const int jw = (w & 3) * 16;      // j-group base (within 64)
    const int mrow = (w >> 2) * 32 + lane;   // m-row within tile

    const float* Wsrc = (gate == 0 ? Wzx : (gate == 1 ? Wrx : Wcx)) + (size_t)j0 * HD;
    const float* bsrc = (gate == 0 ? bz : (gate == 1 ? br : bc)) + j0 + jw;

    float bias[16];
#pragma unroll
    for (int jj = 0; jj < 16; ++jj) bias[jj] = bsrc[jj];

    // load W tile [64][256] -> [64][260]
    for (int i = tid; i < 64 * 64; i += 512) {
        int row = i >> 6, q = i & 63;
        *(float4*)(WS + row * 260 + q * 4) = *(const float4*)(Wsrc + row * 256 + q * 4);
    }

    for (int it = 0; it < 8; ++it) {
        const int m = mg * 8 + it;
        __syncthreads();
        const float* xs = x + (size_t)m * 128 * HD;
        for (int i = tid; i < 8192; i += 512) {
            int row = i >> 6, q = i & 63;
            *(float4*)(XS + row * 260 + q * 4) = *(const float4*)(xs + row * 256 + q * 4);
        }
        __syncthreads();

        ull acc[16];
#pragma unroll
        for (int i = 0; i < 16; ++i) acc[i] = 0ull;

        const float* xrow  = XS + mrow * 260;
        const float* wbase = WS + jw * 260;
#pragma unroll 8
        for (int kq = 0; kq < 64; ++kq) {
            ulonglong2 xv = *(const ulonglong2*)(xrow + kq * 4);
#pragma unroll
            for (int jj = 0; jj < 16; ++jj) {
                ulonglong2 wv = *(const ulonglong2*)(wbase + jj * 260 + kq * 4);
                ffma2(acc[jj], xv.x, wv.x);
                ffma2(acc[jj], xv.y, wv.y);
            }
        }

        float* op = XG_buf + ((size_t)m * 128 + mrow) * 768 + gate * 256 + j0 + jw;
#pragma unroll
        for (int q = 0; q < 4; ++q) {
            float4 o;
            float2 f0 = unpk(acc[q * 4 + 0]);
            float2 f1 = unpk(acc[q * 4 + 1]);
            float2 f2 = unpk(acc[q * 4 + 2]);
            float2 f3 = unpk(acc[q * 4 + 3]);
            o.x = f0.x + f0.y + bias[q * 4 + 0];
            o.y = f1.x + f1.y + bias[q * 4 + 1];
            o.z = f2.x + f2.y + bias[q * 4 + 2];
            o.w = f3.x + f3.y + bias[q * 4 + 3];
            *(float4*)(op + q * 4) = o;
        }
    }
}

// ============================================================================
// Phase 2: recurrence. 32 clusters x 4 CTAs, 512 threads each.
// lane = b(4) x ks(8). Warp owns 8 j-rows in phase1 (z or r), 4 in phase2 (c).
// mbarrier handshakes (no barrier.cluster in the loop).
// ============================================================================
constexpr int R_WH = 0;                    // [192][256] quad-swizzled
constexpr int R_H  = 49152;                // [4][260]   quad-swizzled
constexpr int R_RH = 50192;                // [4][260]   quad-swizzled
constexpr int R_Z  = 51232;                // [4][68]
constexpr int R_MB = 51504;                // 2 mbarriers (16B)
constexpr int REC_FLOATS = R_MB + 4;
constexpr size_t REC_SMEM_BYTES = REC_FLOATS * sizeof(float);   // 206032

__global__ void __cluster_dims__(4, 1, 1) __launch_bounds__(512, 1)
gru_rec(const float* __restrict__ h0,
        const float* __restrict__ Wzh, const float* __restrict__ Wrh,
        const float* __restrict__ Wch, float* __restrict__ out)
{
    extern __shared__ float sm[];

    const int tid  = threadIdx.x;
    const int wid  = tid >> 5;
    const int lane = tid & 31;
    const int b    = lane & 3;       // batch row within cluster
    const int ks   = lane >> 2;      // k-split (0..7), 32 floats each
    const int rank = blockIdx.x & 3;
    const int b0   = (blockIdx.x >> 2) << 2;
    const int j0   = rank << 6;

    // ---- init weights (quad-swizzled) and h0 ----
    {
        const float* whs[3] = {Wzh, Wrh, Wch};
        for (int i = tid; i < 12288; i += 512) {
            int g = i >> 12, rem = i & 4095, row = rem >> 6, q = rem & 63;
            *(float4*)(sm + R_WH + (g * 64 + row) * 256 + swq(q) * 4) =
                *(const float4*)(whs[g] + (size_t)(j0 + row) * 256 + q * 4);
        }
        for (int i = tid; i < 256; i += 512) {
            int bb = i >> 6, q = i & 63;
            *(float4*)(sm + R_H + bb * 260 + swq(q) * 4) =
                *(const float4*)(h0 + (size_t)(b0 + bb) * 256 + q * 4);
        }
    }
    const uint32_t base   = smem_u32(sm);
    const uint32_t mb_rh  = base + (uint32_t)R_MB * 4u;
    const uint32_t mb_h   = mb_rh + 8u;
    if (tid == 0) { mbar_init(mb_rh, 64); mbar_init(mb_h, 64); }
    __syncthreads();
    clu_arrive(); clu_wait();

    uint32_t arr_rh[4], arr_h[4];
#pragma unroll
    for (int p = 0; p < 4; ++p) {
        arr_rh[p] = mapa_rank(mb_rh, p);
        arr_h[p]  = mapa_rank(mb_h, p);
    }

    // phase-1 role: warps 0-7 -> z gate, 8-15 -> r gate; 8 local j-rows each
    const int g1  = wid >> 3;
    const int jr1 = (wid & 7) * 8;
    const float* wp1 = sm + R_WH + (g1 * 64 + jr1) * 256;
    // phase-2 role: all warps -> c gate, 4 local j-rows
    const int jc = wid * 4;
    const float* wp2 = sm + R_WH + (128 + jc) * 256;

    const float* Hb = sm + R_H  + b * 260;
    const float* Rb = sm + R_RH + b * 260;

    // DSMEM push addresses (used by lanes 0..3)
    const int q1 = rank * 16 + (jr1 >> 2);   // 2 quads for phase1 r-push
    const int q2 = rank * 16 + wid;          // 1 quad for phase2 h-push
    uint32_t rhA[2][4], hA[4];
#pragma unroll
    for (int qq = 0; qq < 2; ++qq) {
        uint32_t off = base + (uint32_t)(R_RH + b * 260 + swq(q1 + qq) * 4) * 4u;
#pragma unroll
        for (int p = 0; p < 4; ++p) rhA[qq][p] = mapa_rank(off, p);
    }
    {
        uint32_t off = base + (uint32_t)(R_H + b * 260 + swq(q2) * 4) * 4u;
#pragma unroll
        for (int p = 0; p < 4; ++p) hA[p] = mapa_rank(off, p);
    }

    const float* xg1 = XG_buf + (size_t)(b0 + b) * S * 768 + g1 * 256 + (j0 + jr1);
    const float* xg2 = XG_buf + (size_t)(b0 + b) * S * 768 + 512 + (j0 + jc);
    float* outp = out + (size_t)(b0 + b) * S * 256 + (j0 + jc);

    for (int t = 0; t < S; ++t) {
        const uint32_t par = (uint32_t)(t & 1);

        // prefetch this step's input-side projections (lanes 0..3)
        float4 xa, xb2, xc;
        if (lane < 4) {
            const float* p1 = xg1 + (size_t)t * 768;
            xa  = *(const float4*)p1;
            xb2 = *(const float4*)(p1 + 4);
            xc  = *(const float4*)(xg2 + (size_t)t * 768);
        }

        // ---------- phase 1: z or r gate (h-part) ----------
        ull acc[8];
#pragma unroll
        for (int i = 0; i < 8; ++i) acc[i] = 0ull;
#pragma unroll
        for (int i = 0; i < 8; ++i) {
            const int pq = ks * 8 + ((i + ks) & 7);
            ulonglong2 hv = *(const ulonglong2*)(Hb + pq * 4);
            const float* wp = wp1 + pq * 4;
#pragma unroll
            for (int jj = 0; jj < 8; ++jj) {
                ulonglong2 wv = *(const ulonglong2*)(wp + jj * 256);
                ffma2(acc[jj], hv.x, wv.x);
                ffma2(acc[jj], hv.y, wv.y);
            }
        }
        float sv[8];
#pragma unroll
        for (int o = 0; o < 8; ++o) {
            float2 f = unpk(acc[o]);
            float s = f.x + f.y;
            s += __shfl_xor_sync(0xffffffffu, s, 4);
            s += __shfl_xor_sync(0xffffffffu, s, 8);
            s += __shfl_xor_sync(0xffffffffu, s, 16);
            sv[o] = s;
        }
        if (lane < 4) {
            float xg[8] = {xa.x, xa.y, xa.z, xa.w, xb2.x, xb2.y, xb2.z, xb2.w};
            if (g1 == 0) {
                // z gate: store sigmoid to Zs for phase2 consumers
                float4 z0, z1;
                z0.x = sigm(sv[0] + xg[0]); z0.y = sigm(sv[1] + xg[1]);
                z0.z = sigm(sv[2] + xg[2]); z0.w = sigm(sv[3] + xg[3]);
                z1.x = sigm(sv[4] + xg[4]); z1.y = sigm(sv[5] + xg[5]);
                z1.z = sigm(sv[6] + xg[6]); z1.w = sigm(sv[7] + xg[7]);
                *(float4*)(sm + R_Z + b * 68 + jr1)     = z0;
                *(float4*)(sm + R_Z + b * 68 + jr1 + 4) = z1;
            } else {
                // r gate: rr = sigm * hprev, push to all 4 ranks
                float4 hp0 = *(const float4*)(sm + R_H + b * 260 + swq(q1) * 4);
                float4 hp1 = *(const float4*)(sm + R_H + b * 260 + swq(q1 + 1) * 4);
                float4 r0, r1;
                r0.x = sigm(sv[0] + xg[0]) * hp0.x; r0.y = sigm(sv[1] + xg[1]) * hp0.y;
                r0.z = sigm(sv[2] + xg[2]) * hp0.z; r0.w = sigm(sv[3] + xg[3]) * hp0.w;
                r1.x = sigm(sv[4] + xg[4]) * hp1.x; r1.y = sigm(sv[5] + xg[5]) * hp1.y;
                r1.z = sigm(sv[6] + xg[6]) * hp1.z; r1.w = sigm(sv[7] + xg[7]) * hp1.w;
#pragma unroll
                for (int p = 0; p < 4; ++p) {
                    st_clu_v4(rhA[0][p], r0);
                    st_clu_v4(rhA[1][p], r1);
                }
            }
        }
        __syncwarp();
        if (lane == 0) {
#pragma unroll
            for (int p = 0; p < 4; ++p) mbar_arrive_remote(arr_rh[p]);
        }
        mbar_wait(mb_rh, par);

        // ---------- phase 2: candidate gate ----------
        ull cacc[4] = {0ull, 0ull, 0ull, 0ull};
#pragma unroll
        for (int i = 0; i < 8; ++i) {
            const int pq = ks * 8 + ((i + ks) & 7);
            ulonglong2 rv = *(const ulonglong2*)(Rb + pq * 4);
            const float* wp = wp2 + pq * 4;
#pragma unroll
            for (int jj = 0; jj < 4; ++jj) {
                ulonglong2 wv = *(const ulonglong2*)(wp + jj * 256);
                ffma2(cacc[jj], rv.x, wv.x);
                ffma2(cacc[jj], rv.y, wv.y);
            }
        }
        float cv[4];
#pragma unroll
        for (int o = 0; o < 4; ++o) {
            float2 f = unpk(cacc[o]);
            float s = f.x + f.y;
            s += __shfl_xor_sync(0xffffffffu, s, 4);
            s += __shfl_xor_sync(0xffffffffu, s, 8);
            s += __shfl_xor_sync(0xffffffffu, s, 16);
            cv[o] = s;
        }
        if (lane < 4) {
            float4 hp = *(const float4*)(sm + R_H + b * 260 + swq(q2) * 4);
            float4 zg = *(const float4*)(sm + R_Z + b * 68 + jc);
            float4 hn;
            hn.x = fmaf(zg.x, tanh_f(cv[0] + xc.x) - hp.x, hp.x);
            hn.y = fmaf(zg.y, tanh_f(cv[1] + xc.y) - hp.y, hp.y);
            hn.z = fmaf(zg.z, tanh_f(cv[2] + xc.z) - hp.z, hp.z);
            hn.w = fmaf(zg.w, tanh_f(cv[3] + xc.w) - hp.w, hp.w);
#pragma unroll
            for (int p = 0; p < 4; ++p) st_clu_v4(hA[p], hn);
            *(float4*)(outp + (size_t)t * 256) = hn;
        }
        __syncwarp();
        if (lane == 0) {
#pragma unroll
            for (int p = 0; p < 4; ++p) mbar_arrive_remote(arr_h[p]);
        }
        mbar_wait(mb_h, par);
    }
}

extern "C" void kernel_launch(void* const* d_in, const int* in_sizes, int n_in,
                              void* d_out, int out_size) {
    const float* x   = (const float*)d_in[0];
    const float* h0  = (const float*)d_in[1];
    const float* Wzx = (const float*)d_in[2];
    const float* bz  = (const float*)d_in[3];
    const float* Wzh = (const float*)d_in[4];
    const float* Wrx = (const float*)d_in[5];
    const float* br  = (const float*)d_in[6];
    const float* Wrh = (const float*)d_in[7];
    const float* Wcx = (const float*)d_in[8];
    const float* bc  = (const float*)d_in[9];
    const float* Wch = (const float*)d_in[10];
    float* out = (float*)d_out;

    cudaFuncSetAttribute(xproj_kernel, cudaFuncAttributeMaxDynamicSharedMemorySize,
                         (int)PRE_SMEM_BYTES);
    cudaFuncSetAttribute(gru_rec, cudaFuncAttributeMaxDynamicSharedMemorySize,
                         (int)REC_SMEM_BYTES);

    xproj_kernel<<<12 * 128, 512, PRE_SMEM_BYTES>>>(x, Wzx, bz, Wrx, br, Wcx, bc);
    gru_rec<<<128, 512, REC_SMEM_BYTES>>>(h0, Wzh, Wrh, Wch, out);
}

// round 7
// speedup vs baseline: 1.3923x; 1.3923x over previous
#include <cuda_runtime.h>
#include <cstdint>

using ull = unsigned long long;

constexpr int S  = 1024;
constexpr int HD = 256;
constexpr int NB = 128;

// Precomputed input projections: XG[b][s][gate*256 + j], gate order z,r,c
__device__ float XG_buf[(size_t)NB * S * 768];

__device__ __forceinline__ void ffma2(ull& d, ull a, ull b) {
    asm("fma.rn.f32x2 %0, %1, %2, %0;" : "+l"(d) : "l"(a), "l"(b));
}
__device__ __forceinline__ float2 unpk(ull a) {
    float2 r; asm("mov.b64 {%0, %1}, %2;" : "=f"(r.x), "=f"(r.y) : "l"(a)); return r;
}
__device__ __forceinline__ uint32_t smem_u32(const void* p) {
    uint32_t a;
    asm("{ .reg .u64 t; cvta.to.shared.u64 t, %1; cvt.u32.u64 %0, t; }" : "=r"(a) : "l"(p));
    return a;
}
__device__ __forceinline__ uint32_t mapa_rank(uint32_t addr, uint32_t rank) {
    uint32_t r; asm("mapa.shared::cluster.u32 %0, %1, %2;" : "=r"(r) : "r"(addr), "r"(rank));
    return r;
}
__device__ __forceinline__ void st_clu_v4(uint32_t addr, float4 v) {
    asm volatile("st.shared::cluster.v4.f32 [%0], {%1,%2,%3,%4};"
                 :: "r"(addr), "f"(v.x), "f"(v.y), "f"(v.z), "f"(v.w) : "memory");
}
__device__ __forceinline__ void clu_arrive() {
    asm volatile("barrier.cluster.arrive.aligned;" ::: "memory");
}
__device__ __forceinline__ void clu_wait() {
    asm volatile("barrier.cluster.wait.aligned;" ::: "memory");
}
__device__ __forceinline__ float sigm(float x) { return 1.0f / (1.0f + __expf(-x)); }
__device__ __forceinline__ float tanh_f(float x) {
    x = fminf(fmaxf(x, -15.0f), 15.0f);
    float e = __expf(-2.0f * x);
    return __fdividef(1.0f - e, 1.0f + e);
}
// quad rotation swizzle: logical quad q -> physical quad (rotate within 8-quad group)
__device__ __forceinline__ int swq(int q) { return (q & ~7) | ((q + (q >> 3)) & 7); }

// ============================================================================
// Phase 1: XG = x @ Wg^T + bias  (proven R3 version)
// ============================================================================
constexpr int PRE_SMEM_FLOATS = 32768 + 64 * 260;
constexpr size_t PRE_SMEM_BYTES = PRE_SMEM_FLOATS * sizeof(float);

__global__ void __launch_bounds__(256, 1)
xproj_kernel(const float* __restrict__ x,
             const float* __restrict__ Wzx, const float* __restrict__ bz,
             const float* __restrict__ Wrx, const float* __restrict__ br,
             const float* __restrict__ Wcx, const float* __restrict__ bc)
{
    extern __shared__ float smp[];
    float* XS = smp;            // [128][256]
    float* WS = smp + 32768;    // [64][260]

    const int tid = threadIdx.x, w = tid >> 5, lane = tid & 31;
    const int nt = blockIdx.x % 12, mg = blockIdx.x / 12;
    const int gate = nt >> 2, j0 = (nt & 3) * 64;

    const float* Wsrc = (gate == 0 ? Wzx : (gate == 1 ? Wrx : Wcx)) + (size_t)j0 * HD;
    const float* bsrc = (gate == 0 ? bz : (gate == 1 ? br : bc)) + j0;
    const float b0v = bsrc[lane];
    const float b1v = bsrc[lane + 32];

    for (int i = tid; i < 64 * 64; i += 256) {
        int row = i >> 6, q = i & 63;
        *(float4*)(WS + row * 260 + q * 4) = *(const float4*)(Wsrc + row * 256 + q * 4);
    }

    const int r0 = w * 16;
    for (int it = 0; it < 8; ++it) {
        const int m = mg * 8 + it;
        __syncthreads();
        const float* xs = x + (size_t)m * 128 * HD;
#pragma unroll 8
        for (int i = tid; i < 8192; i += 256)
            *(float4*)(XS + i * 4) = *(const float4*)(xs + (size_t)i * 4);
        __syncthreads();

        ull acc[32];
#pragma unroll
        for (int i = 0; i < 32; ++i) acc[i] = 0ull;

#pragma unroll 4
        for (int kq = 0; kq < 64; ++kq) {
            ulonglong2 wv0 = *(const ulonglong2*)(WS + lane * 260 + kq * 4);
            ulonglong2 wv1 = *(const ulonglong2*)(WS + (lane + 32) * 260 + kq * 4);
#pragma unroll
            for (int r = 0; r < 16; ++r) {
                ulonglong2 xv = *(const ulonglong2*)(XS + (r0 + r) * 256 + kq * 4);
                ffma2(acc[r * 2 + 0], xv.x, wv0.x);
                ffma2(acc[r * 2 + 0], xv.y, wv0.y);
                ffma2(acc[r * 2 + 1], xv.x, wv1.x);
                ffma2(acc[r * 2 + 1], xv.y, wv1.y);
            }
        }

        float* op = XG_buf + ((size_t)m * 128 + r0) * 768 + gate * 256 + j0;
#pragma unroll
        for (int r = 0; r < 16; ++r) {
            float2 f0 = unpk(acc[r * 2 + 0]);
            float2 f1 = unpk(acc[r * 2 + 1]);
            op[(size_t)r * 768 + lane]      = f0.x + f0.y + b0v;
            op[(size_t)r * 768 + lane + 32] = f1.x + f1.y + b1v;
        }
    }
}

// ============================================================================
// Phase 2: recurrence. 32 clusters x 4 CTAs, 512 threads.
// Phase1 (z+r): weights in REGISTERS. thread=(j_l 4 x k_l 8), 2j x 32k, 4 b rows.
// Phase2 (c):   weights in SMEM (R3 layout), lane = b(4) x ks(8), warp = 4 j.
// barrier.cluster x2 per step.
// ============================================================================
constexpr int R_WC = 0;                    // [64][256] c-gate weights, quad-swizzled
constexpr int R_H  = 16384;                // [4][260]  h, quad-swizzled rows
constexpr int R_RH = 17424;                // [4][260]  r*h, quad-swizzled rows
constexpr int R_Z  = 18464;                // [4][68]
constexpr int R_XG = 18736;                // [2][4][3][68] = 1632 floats
constexpr int REC_FLOATS = R_XG + 1632;    // 20368
constexpr size_t REC_SMEM_BYTES = REC_FLOATS * sizeof(float);  // ~81.5 KB

__global__ void __cluster_dims__(4, 1, 1) __launch_bounds__(512, 1)
gru_rec(const float* __restrict__ h0,
        const float* __restrict__ Wzh, const float* __restrict__ Wrh,
        const float* __restrict__ Wch, float* __restrict__ out)
{
    extern __shared__ float sm[];

    const int tid  = threadIdx.x;
    const int wid  = tid >> 5;
    const int lane = tid & 31;
    const int rank = blockIdx.x & 3;
    const int b0   = (blockIdx.x >> 2) << 2;
    const int j0   = rank << 6;

    // phase-1 identity: gate (z:warps0-7, r:warps8-15), 8 j per warp
    const int g1 = wid >> 3;
    const int jb = (wid & 7) * 8;
    const int jl = lane >> 3;        // j-lane 0..3 (2 j each)
    const int kl = lane & 7;         // k-lane 0..7 (32 k each)
    // phase-2 identity: lane = b(4) x ks(8), warp = 4 j of gate c
    const int b2 = lane & 3;
    const int ks = lane >> 2;
    const int jc = wid * 4;

    // ---- init SMEM: Wc (swizzled), h0 (swizzled) ----
    for (int i = tid; i < 4096; i += 512) {
        int row = i >> 6, q = i & 63;
        *(float4*)(sm + R_WC + row * 256 + swq(q) * 4) =
            *(const float4*)(Wch + (size_t)(j0 + row) * 256 + q * 4);
    }
    for (int i = tid; i < 256; i += 512) {
        int bb = i >> 6, q = i & 63;
        *(float4*)(sm + R_H + bb * 260 + swq(q) * 4) =
            *(const float4*)(h0 + (size_t)(b0 + bb) * 256 + q * 4);
    }
    // preload XG for t=0 into buffer 0
    if (tid < 192) {
        int pb = tid / 48, rem = tid % 48, pg = rem >> 4, pq = rem & 15;
        float4 v = *(const float4*)(XG_buf + ((size_t)(b0 + pb) * S + 0) * 768
                                    + pg * 256 + j0 + pq * 4);
        *(float4*)(sm + R_XG + pb * 204 + pg * 68 + pq * 4) = v;
    }

    // ---- phase-1 weights -> registers (2 j x 32 k per thread) ----
    ull w1[32];
    {
        const float* wsrc = (g1 == 0 ? Wzh : Wrh)
                          + (size_t)(j0 + jb + jl * 2) * 256 + kl * 32;
#pragma unroll
        for (int jt = 0; jt < 2; ++jt)
#pragma unroll
            for (int c = 0; c < 4; ++c) {
                ulonglong2 v0 = *(const ulonglong2*)(wsrc + jt * 256 + c * 8);
                ulonglong2 v1 = *(const ulonglong2*)(wsrc + jt * 256 + c * 8 + 4);
                w1[jt * 16 + c * 4 + 0] = v0.x;
                w1[jt * 16 + c * 4 + 1] = v0.y;
                w1[jt * 16 + c * 4 + 2] = v1.x;
                w1[jt * 16 + c * 4 + 3] = v1.y;
            }
    }
    __syncthreads();
    clu_arrive(); clu_wait();

    const uint32_t base = smem_u32(sm);
    uint32_t rbase[4];
#pragma unroll
    for (int p = 0; p < 4; ++p) rbase[p] = mapa_rank(base, p);

    // phase-1 push offsets (bytes), lanes kl==0 && (jl&1)==0
    const int qr = rank * 16 + ((jb + jl * 2) >> 2);
    const uint32_t offRH = (uint32_t)(R_RH + swq(qr) * 4) * 4u;
    // phase-2 push offset: quad rank*16 + wid
    const int qh = rank * 16 + wid;
    const uint32_t offH = (uint32_t)(R_H + swq(qh) * 4) * 4u;

    const float* wp2 = sm + R_WC + jc * 256;
    float* outp = out + (size_t)(b0 + b2) * S * 256 + (j0 + jc);

    // XG producer identity
    const int pb = tid / 48, prem = tid % 48, pg = prem >> 4, pq = prem & 15;
    const float* psrc = XG_buf + (size_t)(b0 + pb) * S * 768 + pg * 256 + j0 + pq * 4;

    for (int t = 0; t < S; ++t) {
        // prefetch next step's XG (global -> regs)
        float4 pxv;
        if (tid < 192 && t + 1 < S)
            pxv = *(const float4*)(psrc + (size_t)(t + 1) * 768);

        const float* xgb = sm + R_XG + (t & 1) * 816;

        // ================= phase 1: z / r gates (register W) =================
        ull acc[8];
#pragma unroll
        for (int i = 0; i < 8; ++i) acc[i] = 0ull;
#pragma unroll
        for (int c = 0; c < 4; ++c) {
#pragma unroll
            for (int b = 0; b < 4; ++b) {
                const float* hb = sm + R_H + b * 260;
                const int p0 = (kl << 3) | ((2 * c + kl) & 7);
                const int p1 = (kl << 3) | ((2 * c + 1 + kl) & 7);
                ulonglong2 h0v = *(const ulonglong2*)(hb + p0 * 4);
                ulonglong2 h1v = *(const ulonglong2*)(hb + p1 * 4);
#pragma unroll
                for (int jt = 0; jt < 2; ++jt) {
                    ffma2(acc[b * 2 + jt], h0v.x, w1[jt * 16 + c * 4 + 0]);
                    ffma2(acc[b * 2 + jt], h0v.y, w1[jt * 16 + c * 4 + 1]);
                    ffma2(acc[b * 2 + jt], h1v.x, w1[jt * 16 + c * 4 + 2]);
                    ffma2(acc[b * 2 + jt], h1v.y, w1[jt * 16 + c * 4 + 3]);
                }
            }
        }
        float s[8];
#pragma unroll
        for (int o = 0; o < 8; ++o) {
            float2 f = unpk(acc[o]);
            float v = f.x + f.y;
            v += __shfl_xor_sync(0xffffffffu, v, 1);
            v += __shfl_xor_sync(0xffffffffu, v, 2);
            v += __shfl_xor_sync(0xffffffffu, v, 4);
            s[o] = v;
        }
        if (kl == 0) {
            if (g1 == 0) {
                // z gate -> SMEM
#pragma unroll
                for (int b = 0; b < 4; ++b)
#pragma unroll
                    for (int jt = 0; jt < 2; ++jt) {
                        int jloc = jb + jl * 2 + jt;
                        sm[R_Z + b * 68 + jloc] =
                            sigm(s[b * 2 + jt] + xgb[b * 204 + jloc]);
                    }
            } else {
                // r gate: rr = sigm * hprev, pack j-quad via partner shfl, push
                float rr[8];
#pragma unroll
                for (int b = 0; b < 4; ++b)
#pragma unroll
                    for (int jt = 0; jt < 2; ++jt) {
                        int jloc = jb + jl * 2 + jt;
                        int e = j0 + jloc;
                        float hp = sm[R_H + b * 260 + swq(e >> 2) * 4 + (e & 3)];
                        rr[b * 2 + jt] =
                            sigm(s[b * 2 + jt] + xgb[b * 204 + 68 + jloc]) * hp;
                    }
                float pr[8];
#pragma unroll
                for (int o = 0; o < 8; ++o)
                    pr[o] = __shfl_xor_sync(0x01010101u, rr[o], 8);
                if ((jl & 1) == 0) {
#pragma unroll
                    for (int b = 0; b < 4; ++b) {
                        float4 v = make_float4(rr[b * 2], rr[b * 2 + 1],
                                               pr[b * 2], pr[b * 2 + 1]);
                        uint32_t off = offRH + (uint32_t)b * 1040u;
#pragma unroll
                        for (int p = 0; p < 4; ++p) st_clu_v4(rbase[p] + off, v);
                    }
                }
            }
        }
        // commit next-step XG while cluster drains
        if (tid < 192 && t + 1 < S)
            *(float4*)(sm + R_XG + ((t + 1) & 1) * 816 + pb * 204 + pg * 68 + pq * 4) = pxv;
        clu_arrive(); clu_wait();

        // ================= phase 2: candidate gate (SMEM W) =================
        const float* Rb = sm + R_RH + b2 * 260;
        ull cacc[4] = {0ull, 0ull, 0ull, 0ull};
#pragma unroll
        for (int i = 0; i < 8; ++i) {
            const int pq2 = ks * 8 + ((i + ks) & 7);
            ulonglong2 rv = *(const ulonglong2*)(Rb + pq2 * 4);
            const float* wp = wp2 + pq2 * 4;
#pragma unroll
            for (int jj = 0; jj < 4; ++jj) {
                ulonglong2 wv = *(const ulonglong2*)(wp + jj * 256);
                ffma2(cacc[jj], rv.x, wv.x);
                ffma2(cacc[jj], rv.y, wv.y);
            }
        }
        float cv[4];
#pragma unroll
        for (int o = 0; o < 4; ++o) {
            float2 f = unpk(cacc[o]);
            float v = f.x + f.y;
            v += __shfl_xor_sync(0xffffffffu, v, 4);
            v += __shfl_xor_sync(0xffffffffu, v, 8);
            v += __shfl_xor_sync(0xffffffffu, v, 16);
            cv[o] = v;
        }
        if (lane < 4) {
            float4 hp = *(const float4*)(sm + R_H + b2 * 260 + swq(qh) * 4);
            float4 zg = *(const float4*)(sm + R_Z + b2 * 68 + jc);
            const float* xc = xgb + b2 * 204 + 136 + jc;
            float4 hn;
            hn.x = fmaf(zg.x, tanh_f(cv[0] + xc[0]) - hp.x, hp.x);
            hn.y = fmaf(zg.y, tanh_f(cv[1] + xc[1]) - hp.y, hp.y);
            hn.z = fmaf(zg.z, tanh_f(cv[2] + xc[2]) - hp.z, hp.z);
            hn.w = fmaf(zg.w, tanh_f(cv[3] + xc[3]) - hp.w, hp.w);
            uint32_t off = offH + (uint32_t)b2 * 1040u;
#pragma unroll
            for (int p = 0; p < 4; ++p) st_clu_v4(rbase[p] + off, hn);
            *(float4*)(outp + (size_t)t * 256) = hn;
        }
        clu_arrive(); clu_wait();
    }
}

extern "C" void kernel_launch(void* const* d_in, const int* in_sizes, int n_in,
                              void* d_out, int out_size) {
    const float* x   = (const float*)d_in[0];
    const float* h0  = (const float*)d_in[1];
    const float* Wzx = (const float*)d_in[2];
    const float* bz  = (const float*)d_in[3];
    const float* Wzh = (const float*)d_in[4];
    const float* Wrx = (const float*)d_in[5];
    const float* br  = (const float*)d_in[6];
    const float* Wrh = (const float*)d_in[7];
    const float* Wcx = (const float*)d_in[8];
    const float* bc  = (const float*)d_in[9];
    const float* Wch = (const float*)d_in[10];
    float* out = (float*)d_out;

    cudaFuncSetAttribute(xproj_kernel, cudaFuncAttributeMaxDynamicSharedMemorySize,
                         (int)PRE_SMEM_BYTES);
    cudaFuncSetAttribute(gru_rec, cudaFuncAttributeMaxDynamicSharedMemorySize,
                         (int)REC_SMEM_BYTES);

    xproj_kernel<<<12 * 128, 256, PRE_SMEM_BYTES>>>(x, Wzx, bz, Wrx, br, Wcx, bc);
    gru_rec<<<128, 512, REC_SMEM_BYTES>>>(h0, Wzh, Wrh, Wch, out);
}

// round 8
// speedup vs baseline: 1.3930x; 1.0005x over previous
#include <cuda_runtime.h>
#include <cstdint>

using ull = unsigned long long;

constexpr int S  = 1024;
constexpr int HD = 256;
constexpr int NB = 128;

// Precomputed input projections: XG[b][s][gate*256 + j], gate order z,r,c
__device__ float XG_buf[(size_t)NB * S * 768];

__device__ __forceinline__ void ffma2(ull& d, ull a, ull b) {
    asm("fma.rn.f32x2 %0, %1, %2, %0;" : "+l"(d) : "l"(a), "l"(b));
}
__device__ __forceinline__ float2 unpk(ull a) {
    float2 r; asm("mov.b64 {%0, %1}, %2;" : "=f"(r.x), "=f"(r.y) : "l"(a)); return r;
}
__device__ __forceinline__ uint32_t smem_u32(const void* p) {
    uint32_t a;
    asm("{ .reg .u64 t; cvta.to.shared.u64 t, %1; cvt.u32.u64 %0, t; }" : "=r"(a) : "l"(p));
    return a;
}
__device__ __forceinline__ uint32_t mapa_rank(uint32_t addr, uint32_t rank) {
    uint32_t r; asm("mapa.shared::cluster.u32 %0, %1, %2;" : "=r"(r) : "r"(addr), "r"(rank));
    return r;
}
__device__ __forceinline__ void st_clu_v4(uint32_t addr, float4 v) {
    asm volatile("st.shared::cluster.v4.f32 [%0], {%1,%2,%3,%4};"
                 :: "r"(addr), "f"(v.x), "f"(v.y), "f"(v.z), "f"(v.w) : "memory");
}
__device__ __forceinline__ void clu_arrive() {
    asm volatile("barrier.cluster.arrive.aligned;" ::: "memory");
}
__device__ __forceinline__ void clu_wait() {
    asm volatile("barrier.cluster.wait.aligned;" ::: "memory");
}
__device__ __forceinline__ float sigm(float x) { return 1.0f / (1.0f + __expf(-x)); }
__device__ __forceinline__ float tanh_f(float x) {
    x = fminf(fmaxf(x, -15.0f), 15.0f);
    float e = __expf(-2.0f * x);
    return __fdividef(1.0f - e, 1.0f + e);
}
// quad rotation swizzle: logical quad q -> physical quad (rotate within 8-quad group)
__device__ __forceinline__ int swq(int q) { return (q & ~7) | ((q + (q >> 3)) & 7); }

// ============================================================================
// Phase 1: XG = x @ Wg^T + bias  (proven R3 version)
// ============================================================================
constexpr int PRE_SMEM_FLOATS = 32768 + 64 * 260;
constexpr size_t PRE_SMEM_BYTES = PRE_SMEM_FLOATS * sizeof(float);

__global__ void __launch_bounds__(256, 1)
xproj_kernel(const float* __restrict__ x,
             const float* __restrict__ Wzx, const float* __restrict__ bz,
             const float* __restrict__ Wrx, const float* __restrict__ br,
             const float* __restrict__ Wcx, const float* __restrict__ bc)
{
    extern __shared__ float smp[];
    float* XS = smp;            // [128][256]
    float* WS = smp + 32768;    // [64][260]

    const int tid = threadIdx.x, w = tid >> 5, lane = tid & 31;
    const int nt = blockIdx.x % 12, mg = blockIdx.x / 12;
    const int gate = nt >> 2, j0 = (nt & 3) * 64;

    const float* Wsrc = (gate == 0 ? Wzx : (gate == 1 ? Wrx : Wcx)) + (size_t)j0 * HD;
    const float* bsrc = (gate == 0 ? bz : (gate == 1 ? br : bc)) + j0;
    const float b0v = bsrc[lane];
    const float b1v = bsrc[lane + 32];

    for (int i = tid; i < 64 * 64; i += 256) {
        int row = i >> 6, q = i & 63;
        *(float4*)(WS + row * 260 + q * 4) = *(const float4*)(Wsrc + row * 256 + q * 4);
    }

    const int r0 = w * 16;
    for (int it = 0; it < 8; ++it) {
        const int m = mg * 8 + it;
        __syncthreads();
        const float* xs = x + (size_t)m * 128 * HD;
#pragma unroll 8
        for (int i = tid; i < 8192; i += 256)
            *(float4*)(XS + i * 4) = *(const float4*)(xs + (size_t)i * 4);
        __syncthreads();

        ull acc[32];
#pragma unroll
        for (int i = 0; i < 32; ++i) acc[i] = 0ull;

#pragma unroll 4
        for (int kq = 0; kq < 64; ++kq) {
            ulonglong2 wv0 = *(const ulonglong2*)(WS + lane * 260 + kq * 4);
            ulonglong2 wv1 = *(const ulonglong2*)(WS + (lane + 32) * 260 + kq * 4);
#pragma unroll
            for (int r = 0; r < 16; ++r) {
                ulonglong2 xv = *(const ulonglong2*)(XS + (r0 + r) * 256 + kq * 4);
                ffma2(acc[r * 2 + 0], xv.x, wv0.x);
                ffma2(acc[r * 2 + 0], xv.y, wv0.y);
                ffma2(acc[r * 2 + 1], xv.x, wv1.x);
                ffma2(acc[r * 2 + 1], xv.y, wv1.y);
            }
        }

        float* op = XG_buf + ((size_t)m * 128 + r0) * 768 + gate * 256 + j0;
#pragma unroll
        for (int r = 0; r < 16; ++r) {
            float2 f0 = unpk(acc[r * 2 + 0]);
            float2 f1 = unpk(acc[r * 2 + 1]);
            op[(size_t)r * 768 + lane]      = f0.x + f0.y + b0v;
            op[(size_t)r * 768 + lane + 32] = f1.x + f1.y + b1v;
        }
    }
}

// ============================================================================
// Phase 2: recurrence. 32 clusters x 4 CTAs, 512 threads.
// Phase1 (z+r): weights in REGISTERS. thread=(j_l 4 x k_l 8), 2j x 32k, 4 b rows.
// Phase2 (c):   weights in SMEM (R3 layout), lane = b(4) x ks(8), warp = 4 j.
// barrier.cluster x2 per step.
// ============================================================================
constexpr int R_WC = 0;                    // [64][256] c-gate weights, quad-swizzled
constexpr int R_H  = 16384;                // [4][260]  h, quad-swizzled rows
constexpr int R_RH = 17424;                // [4][260]  r*h, quad-swizzled rows
constexpr int R_Z  = 18464;                // [4][68]
constexpr int R_XG = 18736;                // [2][4][3][68] = 1632 floats
constexpr int REC_FLOATS = R_XG + 1632;    // 20368
constexpr size_t REC_SMEM_BYTES = REC_FLOATS * sizeof(float);  // ~81.5 KB

__global__ void __cluster_dims__(4, 1, 1) __launch_bounds__(512, 1)
gru_rec(const float* __restrict__ h0,
        const float* __restrict__ Wzh, const float* __restrict__ Wrh,
        const float* __restrict__ Wch, float* __restrict__ out)
{
    extern __shared__ float sm[];

    const int tid  = threadIdx.x;
    const int wid  = tid >> 5;
    const int lane = tid & 31;
    const int rank = blockIdx.x & 3;
    const int b0   = (blockIdx.x >> 2) << 2;
    const int j0   = rank << 6;

    // phase-1 identity: gate (z:warps0-7, r:warps8-15), 8 j per warp
    const int g1 = wid >> 3;
    const int jb = (wid & 7) * 8;
    const int jl = lane >> 3;        // j-lane 0..3 (2 j each)
    const int kl = lane & 7;         // k-lane 0..7 (32 k each)
    // phase-2 identity: lane = b(4) x ks(8), warp = 4 j of gate c
    const int b2 = lane & 3;
    const int ks = lane >> 2;
    const int jc = wid * 4;

    // ---- init SMEM: Wc (swizzled), h0 (swizzled) ----
    for (int i = tid; i < 4096; i += 512) {
        int row = i >> 6, q = i & 63;
        *(float4*)(sm + R_WC + row * 256 + swq(q) * 4) =
            *(const float4*)(Wch + (size_t)(j0 + row) * 256 + q * 4);
    }
    for (int i = tid; i < 256; i += 512) {
        int bb = i >> 6, q = i & 63;
        *(float4*)(sm + R_H + bb * 260 + swq(q) * 4) =
            *(const float4*)(h0 + (size_t)(b0 + bb) * 256 + q * 4);
    }
    // preload XG for t=0 into buffer 0
    if (tid < 192) {
        int pb = tid / 48, rem = tid % 48, pg = rem >> 4, pq = rem & 15;
        float4 v = *(const float4*)(XG_buf + ((size_t)(b0 + pb) * S + 0) * 768
                                    + pg * 256 + j0 + pq * 4);
        *(float4*)(sm + R_XG + pb * 204 + pg * 68 + pq * 4) = v;
    }

    // ---- phase-1 weights -> registers (2 j x 32 k per thread) ----
    ull w1[32];
    {
        const float* wsrc = (g1 == 0 ? Wzh : Wrh)
                          + (size_t)(j0 + jb + jl * 2) * 256 + kl * 32;
#pragma unroll
        for (int jt = 0; jt < 2; ++jt)
#pragma unroll
            for (int c = 0; c < 4; ++c) {
                ulonglong2 v0 = *(const ulonglong2*)(wsrc + jt * 256 + c * 8);
                ulonglong2 v1 = *(const ulonglong2*)(wsrc + jt * 256 + c * 8 + 4);
                w1[jt * 16 + c * 4 + 0] = v0.x;
                w1[jt * 16 + c * 4 + 1] = v0.y;
                w1[jt * 16 + c * 4 + 2] = v1.x;
                w1[jt * 16 + c * 4 + 3] = v1.y;
            }
    }
    __syncthreads();
    clu_arrive(); clu_wait();

    const uint32_t base = smem_u32(sm);
    uint32_t rbase[4];
#pragma unroll
    for (int p = 0; p < 4; ++p) rbase[p] = mapa_rank(base, p);

    // phase-1 push offsets (bytes), lanes kl==0 && (jl&1)==0
    const int qr = rank * 16 + ((jb + jl * 2) >> 2);
    const uint32_t offRH = (uint32_t)(R_RH + swq(qr) * 4) * 4u;
    // phase-2 push offset: quad rank*16 + wid
    const int qh = rank * 16 + wid;
    const uint32_t offH = (uint32_t)(R_H + swq(qh) * 4) * 4u;

    const float* wp2 = sm + R_WC + jc * 256;
    float* outp = out + (size_t)(b0 + b2) * S * 256 + (j0 + jc);

    // XG producer identity
    const int pb = tid / 48, prem = tid % 48, pg = prem >> 4, pq = prem & 15;
    const float* psrc = XG_buf + (size_t)(b0 + pb) * S * 768 + pg * 256 + j0 + pq * 4;

    for (int t = 0; t < S; ++t) {
        // prefetch next step's XG (global -> regs)
        float4 pxv;
        if (tid < 192 && t + 1 < S)
            pxv = *(const float4*)(psrc + (size_t)(t + 1) * 768);

        const float* xgb = sm + R_XG + (t & 1) * 816;

        // ================= phase 1: z / r gates (register W) =================
        ull acc[8];
#pragma unroll
        for (int i = 0; i < 8; ++i) acc[i] = 0ull;
#pragma unroll
        for (int c = 0; c < 4; ++c) {
#pragma unroll
            for (int b = 0; b < 4; ++b) {
                const float* hb = sm + R_H + b * 260;
                const int p0 = (kl << 3) | ((2 * c + kl) & 7);
                const int p1 = (kl << 3) | ((2 * c + 1 + kl) & 7);
                ulonglong2 h0v = *(const ulonglong2*)(hb + p0 * 4);
                ulonglong2 h1v = *(const ulonglong2*)(hb + p1 * 4);
#pragma unroll
                for (int jt = 0; jt < 2; ++jt) {
                    ffma2(acc[b * 2 + jt], h0v.x, w1[jt * 16 + c * 4 + 0]);
                    ffma2(acc[b * 2 + jt], h0v.y, w1[jt * 16 + c * 4 + 1]);
                    ffma2(acc[b * 2 + jt], h1v.x, w1[jt * 16 + c * 4 + 2]);
                    ffma2(acc[b * 2 + jt], h1v.y, w1[jt * 16 + c * 4 + 3]);
                }
            }
        }
        float s[8];
#pragma unroll
        for (int o = 0; o < 8; ++o) {
            float2 f = unpk(acc[o]);
            float v = f.x + f.y;
            v += __shfl_xor_sync(0xffffffffu, v, 1);
            v += __shfl_xor_sync(0xffffffffu, v, 2);
            v += __shfl_xor_sync(0xffffffffu, v, 4);
            s[o] = v;
        }
        if (kl == 0) {
            if (g1 == 0) {
                // z gate -> SMEM
#pragma unroll
                for (int b = 0; b < 4; ++b)
#pragma unroll
                    for (int jt = 0; jt < 2; ++jt) {
                        int jloc = jb + jl * 2 + jt;
                        sm[R_Z + b * 68 + jloc] =
                            sigm(s[b * 2 + jt] + xgb[b * 204 + jloc]);
                    }
            } else {
                // r gate: rr = sigm * hprev, pack j-quad via partner shfl, push
                float rr[8];
#pragma unroll
                for (int b = 0; b < 4; ++b)
#pragma unroll
                    for (int jt = 0; jt < 2; ++jt) {
                        int jloc = jb + jl * 2 + jt;
                        int e = j0 + jloc;
                        float hp = sm[R_H + b * 260 + swq(e >> 2) * 4 + (e & 3)];
                        rr[b * 2 + jt] =
                            sigm(s[b * 2 + jt] + xgb[b * 204 + 68 + jloc]) * hp;
                    }
                float pr[8];
#pragma unroll
                for (int o = 0; o < 8; ++o)
                    pr[o] = __shfl_xor_sync(0x01010101u, rr[o], 8);
                if ((jl & 1) == 0) {
#pragma unroll
                    for (int b = 0; b < 4; ++b) {
                        float4 v = make_float4(rr[b * 2], rr[b * 2 + 1],
                                               pr[b * 2], pr[b * 2 + 1]);
                        uint32_t off = offRH + (uint32_t)b * 1040u;
#pragma unroll
                        for (int p = 0; p < 4; ++p) st_clu_v4(rbase[p] + off, v);
                    }
                }
            }
        }
        // commit next-step XG while cluster drains
        if (tid < 192 && t + 1 < S)
            *(float4*)(sm + R_XG + ((t + 1) & 1) * 816 + pb * 204 + pg * 68 + pq * 4) = pxv;
        clu_arrive(); clu_wait();

        // ================= phase 2: candidate gate (SMEM W) =================
        const float* Rb = sm + R_RH + b2 * 260;
        ull cacc[4] = {0ull, 0ull, 0ull, 0ull};
#pragma unroll
        for (int i = 0; i < 8; ++i) {
            const int pq2 = ks * 8 + ((i + ks) & 7);
            ulonglong2 rv = *(const ulonglong2*)(Rb + pq2 * 4);
            const float* wp = wp2 + pq2 * 4;
#pragma unroll
            for (int jj = 0; jj < 4; ++jj) {
                ulonglong2 wv = *(const ulonglong2*)(wp + jj * 256);
                ffma2(cacc[jj], rv.x, wv.x);
                ffma2(cacc[jj], rv.y, wv.y);
            }
        }
        float cv[4];
#pragma unroll
        for (int o = 0; o < 4; ++o) {
            float2 f = unpk(cacc[o]);
            float v = f.x + f.y;
            v += __shfl_xor_sync(0xffffffffu, v, 4);
            v += __shfl_xor_sync(0xffffffffu, v, 8);
            v += __shfl_xor_sync(0xffffffffu, v, 16);
            cv[o] = v;
        }
        if (lane < 4) {
            float4 hp = *(const float4*)(sm + R_H + b2 * 260 + swq(qh) * 4);
            float4 zg = *(const float4*)(sm + R_Z + b2 * 68 + jc);
            const float* xc = xgb + b2 * 204 + 136 + jc;
            float4 hn;
            hn.x = fmaf(zg.x, tanh_f(cv[0] + xc[0]) - hp.x, hp.x);
            hn.y = fmaf(zg.y, tanh_f(cv[1] + xc[1]) - hp.y, hp.y);
            hn.z = fmaf(zg.z, tanh_f(cv[2] + xc[2]) - hp.z, hp.z);
            hn.w = fmaf(zg.w, tanh_f(cv[3] + xc[3]) - hp.w, hp.w);
            uint32_t off = offH + (uint32_t)b2 * 1040u;
#pragma unroll
            for (int p = 0; p < 4; ++p) st_clu_v4(rbase[p] + off, hn);
            *(float4*)(outp + (size_t)t * 256) = hn;
        }
        clu_arrive(); clu_wait();
    }
}

extern "C" void kernel_launch(void* const* d_in, const int* in_sizes, int n_in,
                              void* d_out, int out_size) {
    const float* x   = (const float*)d_in[0];
    const float* h0  = (const float*)d_in[1];
    const float* Wzx = (const float*)d_in[2];
    const float* bz  = (const float*)d_in[3];
    const float* Wzh = (const float*)d_in[4];
    const float* Wrx = (const float*)d_in[5];
    const float* br  = (const float*)d_in[6];
    const float* Wrh = (const float*)d_in[7];
    const float* Wcx = (const float*)d_in[8];
    const float* bc  = (const float*)d_in[9];
    const float* Wch = (const float*)d_in[10];
    float* out = (float*)d_out;

    cudaFuncSetAttribute(xproj_kernel, cudaFuncAttributeMaxDynamicSharedMemorySize,
                         (int)PRE_SMEM_BYTES);
    cudaFuncSetAttribute(gru_rec, cudaFuncAttributeMaxDynamicSharedMemorySize,
                         (int)REC_SMEM_BYTES);

    xproj_kernel<<<12 * 128, 256, PRE_SMEM_BYTES>>>(x, Wzx, bz, Wrx, br, Wcx, bc);
    gru_rec<<<128, 512, REC_SMEM_BYTES>>>(h0, Wzh, Wrh, Wch, out);
}